// round 17
// baseline (speedup 1.0000x reference)
#include <cuda_runtime.h>
#include <cuda_fp16.h>
#include <cstdint>
#include <math.h>

// ---------------- problem constants ----------------
#define S_LEN 2048
#define BHN   64          // B*H
#define DQ    64
#define DP    32
#define KC    96          // concatenated K (q|pq)
#define LOG2E 1.4426950408889634f
#define SCALE_Q (0.125f * LOG2E)               // exp2-folded
#define SCALE_P (0.17677669529663687f * LOG2E) // exp2-folded

#define THREADS 256       // 8 warps; 2 CTAs per SM
#define NWARP  8
#define MROWS 16          // rows per tile (full 2048-wide ownership)
#define NSUB  64          // columns per subtile (8 warps x n8)
#define NSUBS 32          // 2048 / 64
#define NTILES ((S_LEN / MROWS) * BHN)   // 8192
#define NCTA  296         // persistent CTAs (2 per SM)
#define SPADB 208         // A/B smem row stride bytes (13*16B, ldmatrix-clean)
#define NSTG  3           // B ring stages per warp
#define WSTAGE 1664       // per-warp per-stage bytes (8 rows * 208)
#define WSLAB  (NSTG * WSTAGE)        // 4992 B per warp
#define SROWB  4112       // score smem row stride (4096 + 16 skew)

#define SM_A    0                     // A: 16*208 = 3328
#define SM_RED  3328                  // redp 16*8*4 = 512 + rsum 64 = 576
#define SM_SC   3904                  // scores: 16 * 4112 = 65792
#define SM_B    69696                 // B slabs: 8 * 4992 = 39936
#define SM_TOT  109632                // x2 CTAs = 219264 <= 228KB

// fp16 scratch: [bh][s][96]  (clamp+scale(+log2e on A) folded)
__device__ __align__(16) __half g_Ah[(size_t)BHN * S_LEN * KC];
__device__ __align__(16) __half g_Bh[(size_t)BHN * S_LEN * KC];

__device__ __forceinline__ float clamp5(float x) {
    return fminf(fmaxf(x, -5.0f), 5.0f);
}

__device__ __forceinline__ float ex2f(float x) {     // single MUFU.EX2
    float y;
    asm("ex2.approx.f32 %0, %1;" : "=f"(y) : "f"(x));
    return y;
}

__device__ __forceinline__ uint32_t h2_to_u32(__half2 h) {
    union { __half2 h; uint32_t u; } cv;
    cv.h = h;
    return cv.u;
}

__device__ __forceinline__ uint32_t smem_u32(const void* p) {
    uint32_t a;
    asm("{ .reg .u64 t; cvta.to.shared.u64 t, %1; cvt.u32.u64 %0, t; }" : "=r"(a) : "l"(p));
    return a;
}
__device__ __forceinline__ void cp16(uint32_t dst, const void* src) {
    asm volatile("cp.async.cg.shared.global [%0], [%1], 16;" :: "r"(dst), "l"(src));
}
#define CP_COMMIT() asm volatile("cp.async.commit_group;" ::: "memory")
#define CP_WAIT1()  asm volatile("cp.async.wait_group 1;" ::: "memory")

__device__ __forceinline__ void ldsm_x4(uint32_t* r, uint32_t addr) {
    asm volatile("ldmatrix.sync.aligned.m8n8.x4.shared.b16 {%0,%1,%2,%3}, [%4];"
                 : "=r"(r[0]), "=r"(r[1]), "=r"(r[2]), "=r"(r[3]) : "r"(addr));
}
__device__ __forceinline__ void mma_fp16(float* d, const uint32_t* a, const uint32_t* b) {
    asm volatile("mma.sync.aligned.m16n8k16.row.col.f32.f16.f16.f32 "
                 "{%0,%1,%2,%3}, {%4,%5,%6,%7}, {%8,%9}, {%0,%1,%2,%3};"
                 : "+f"(d[0]), "+f"(d[1]), "+f"(d[2]), "+f"(d[3])
                 : "r"(a[0]), "r"(a[1]), "r"(a[2]), "r"(a[3]), "r"(b[0]), "r"(b[1]));
}

// ---------------------------------------------------------------------------
// Pass 0: clamp + scale(+log2e on A) + fp16 convert; float4-vectorized.
// ---------------------------------------------------------------------------
__global__ __launch_bounds__(256) void prep_fp16(
    const float* __restrict__ keys, const float* __restrict__ queries,
    const float* __restrict__ pos_key, const float* __restrict__ pos_query)
{
    size_t idx4 = (size_t)blockIdx.x * blockDim.x + threadIdx.x;
    const size_t total4 = (size_t)BHN * S_LEN * (KC / 4);
    if (idx4 >= total4) return;
    size_t row = idx4 / (KC / 4);
    int c0 = (int)(idx4 % (KC / 4)) * 4;
    float4 va, vb;
    if (c0 < DQ) {
        va = *(const float4*)(queries + row * DQ + c0);
        vb = *(const float4*)(keys + row * DQ + c0);
        va.x = clamp5(va.x) * SCALE_Q; va.y = clamp5(va.y) * SCALE_Q;
        va.z = clamp5(va.z) * SCALE_Q; va.w = clamp5(va.w) * SCALE_Q;
    } else {
        va = *(const float4*)(pos_query + row * DP + (c0 - DQ));
        vb = *(const float4*)(pos_key + row * DP + (c0 - DQ));
        va.x = clamp5(va.x) * SCALE_P; va.y = clamp5(va.y) * SCALE_P;
        va.z = clamp5(va.z) * SCALE_P; va.w = clamp5(va.w) * SCALE_P;
    }
    vb.x = clamp5(vb.x); vb.y = clamp5(vb.y);
    vb.z = clamp5(vb.z); vb.w = clamp5(vb.w);
    *(__half2*)(g_Ah + row * KC + c0)     = __floats2half2_rn(va.x, va.y);
    *(__half2*)(g_Ah + row * KC + c0 + 2) = __floats2half2_rn(va.z, va.w);
    *(__half2*)(g_Bh + row * KC + c0)     = __floats2half2_rn(vb.x, vb.y);
    *(__half2*)(g_Bh + row * KC + c0 + 2) = __floats2half2_rn(vb.z, vb.w);
}

// ---------------------------------------------------------------------------
// Pass 1 (fused, persistent, 2 CTAs/SM): per tile 16x2048 scores -> exp2
// (fp16 smem) -> fp32 rowsum -> normalized single-pass write. 8 warps,
// subtile 64 wide (warp n8); warp-private 3-stage cp.async B ring; B frags
// software-pipelined across iterations. Two CTAs per SM: one CTA's
// epilogue/barriers overlap the other's mainloop.
// Ledger: 2 prologue commits, one commit per iter -> wait_group 1 at global
// stage L guarantees stage L landed.
// ---------------------------------------------------------------------------
__global__ __launch_bounds__(THREADS, 2) void fused_attn(float* __restrict__ out)
{
    extern __shared__ __align__(16) char smraw[];
    float* redp = (float*)(smraw + SM_RED);          // [16 rows][8 warps]
    float* rsum = redp + 16 * NWARP;                 // [16] inverse sums
    const uint32_t sA  = smem_u32(smraw + SM_A);
    const uint32_t sSC = smem_u32(smraw + SM_SC);

    const int tid = threadIdx.x;
    const int lane = tid & 31, warp = tid >> 5;      // 8 warps
    const int bid = blockIdx.x;

    const uint32_t slab = smem_u32(smraw + SM_B) + warp * WSLAB;

    const int r0 = lane >> 2;                       // 0..7
    const int c2 = (lane & 3) * 2;
    const uint32_t bfoff = (lane & 7) * SPADB + (lane >> 3) * 16;
    const uint32_t scbase = sSC + (warp * 8 + c2) * 2;   // + row*SROWB + s*128

    // per-lane B chunk coords (3 chunks of 16B per lane per stage; 96 total)
    int br[3], bc[3];
    #pragma unroll
    for (int i = 0; i < 3; i++) {
        int f = lane + i * 32;
        br[i] = f / 12;  bc[i] = f % 12;
    }

    // --- first-tile prologue ---
    {
        const int bh0 = bid >> 7;
        const __half* Bg0 = g_Bh + (size_t)bh0 * S_LEN * KC;
        #pragma unroll
        for (int j = 0; j < 2; j++) {          // B stages 0,1 -> slots 0,1
            #pragma unroll
            for (int i = 0; i < 3; i++)
                cp16(slab + j * WSTAGE + br[i] * SPADB + bc[i] * 16,
                     (const char*)Bg0 + ((size_t)j * NSUB + warp * 8 + br[i]) * (KC * 2) + bc[i] * 16);
            CP_COMMIT();
        }
        const int mt0 = bid & 127;
        const __half* Ag0 = g_Ah + ((size_t)bh0 * S_LEN + (size_t)mt0 * MROWS) * KC;
        if (tid < 192) {
            int row = tid / 12, c = tid % 12;
            uint4 v = *(const uint4*)((const char*)Ag0 + (size_t)row * (KC * 2) + c * 16);
            *(uint4*)(smraw + SM_A + row * SPADB + c * 16) = v;
        }
        __syncthreads();
    }

    int slot = 0;                                // slot of frags currently in b

    for (int T = bid; T < NTILES; T += NCTA) {
        const int bh = T >> 7, mt = T & 127;
        const __half* Bg = g_Bh + (size_t)bh * S_LEN * KC;
        const int T2 = T + NCTA;
        const bool hasNext = (T2 < NTILES);
        const __half* Bg2 = hasNext ? g_Bh + (size_t)(T2 >> 7) * S_LEN * KC : (const __half*)0;

        // --- A fragments for this tile (rows 0-15, 6 k-steps) ---
        uint32_t aF[6][4];
        {
            const uint32_t ab = sA + (lane & 15) * SPADB + ((lane >> 4) << 3) * 2;
            #pragma unroll
            for (int k = 0; k < 6; k++)
                ldsm_x4(aF[k], ab + k * 32);
        }

        // --- preload B frags for this tile's subtile 0 ---
        uint32_t b[3][4];
        {
            CP_WAIT1();
            __syncwarp();
            const uint32_t bb = slab + slot * WSTAGE + bfoff;
            #pragma unroll
            for (int j = 0; j < 3; j++)
                ldsm_x4(b[j], bb + j * 64);
        }

        float s0 = 0.0f, s1 = 0.0f;

        #pragma unroll 4
        for (int s = 0; s < NSUBS; s++) {
            // (1) issue prefetch for stage L+2; commit always
            {
                const int pfslot = (slot + 2 >= NSTG) ? slot + 2 - NSTG : slot + 2;
                const __half* Bp = (s < NSUBS - 2) ? Bg : Bg2;
                const int sub = (s + 2) & (NSUBS - 1);
                if (Bp) {
                    #pragma unroll
                    for (int i = 0; i < 3; i++)
                        cp16(slab + pfslot * WSTAGE + br[i] * SPADB + bc[i] * 16,
                             (const char*)Bp + ((size_t)sub * NSUB + warp * 8 + br[i]) * (KC * 2) + bc[i] * 16);
                }
                CP_COMMIT();
            }

            // (2) MMA with current frags (2 independent chains of 3)
            float A0[4] = {0,0,0,0}, A1[4] = {0,0,0,0};
            #pragma unroll
            for (int j = 0; j < 3; j++) {
                mma_fp16(A0, aF[2 * j],     &b[j][0]);
                mma_fp16(A1, aF[2 * j + 1], &b[j][2]);
            }

            // (3) wait + load NEXT iter's frags (overlaps in-flight HMMAs)
            if (s < NSUBS - 1) {
                CP_WAIT1();
                __syncwarp();
                slot = (slot + 1 >= NSTG) ? 0 : slot + 1;
                const uint32_t bb = slab + slot * WSTAGE + bfoff;
                #pragma unroll
                for (int j = 0; j < 3; j++)
                    ldsm_x4(b[j], bb + j * 64);
            }

            // (4) exp2 -> fp16 scores to smem; fp32 sums in regs
            float v0 = ex2f(A0[0] + A1[0]), v1 = ex2f(A0[1] + A1[1]);
            float v2 = ex2f(A0[2] + A1[2]), v3 = ex2f(A0[3] + A1[3]);
            s0 += v0 + v1;
            s1 += v2 + v3;

            const uint32_t scs = scbase + s * (NSUB * 2);
            asm volatile("st.shared.b32 [%0], %1;" :: "r"(scs + r0 * SROWB),
                         "r"(h2_to_u32(__floats2half2_rn(v0, v1))) : "memory");
            asm volatile("st.shared.b32 [%0], %1;" :: "r"(scs + (r0 + 8) * SROWB),
                         "r"(h2_to_u32(__floats2half2_rn(v2, v3))) : "memory");
        }
        // advance slot past this tile's last stage for next tile's preload
        slot = (slot + 1 >= NSTG) ? 0 : slot + 1;

        // --- deterministic row sums ---
        s0 += __shfl_xor_sync(0xffffffffu, s0, 1);
        s0 += __shfl_xor_sync(0xffffffffu, s0, 2);
        s1 += __shfl_xor_sync(0xffffffffu, s1, 1);
        s1 += __shfl_xor_sync(0xffffffffu, s1, 2);
        if ((lane & 3) == 0) {
            redp[r0 * NWARP + warp] = s0;
            redp[(r0 + 8) * NWARP + warp] = s1;
        }
        __syncthreads();
        if (tid < MROWS) {
            float t = 0.0f;
            #pragma unroll
            for (int w = 0; w < NWARP; w++) t += redp[tid * NWARP + w];
            rsum[tid] = 1.0f / t;
        }
        __syncthreads();

        // --- prefetch A(next tile) into registers (hides under epilogue) ---
        uint4 av;
        if (hasNext && tid < 192) {
            const __half* Ag2 = g_Ah + ((size_t)(T2 >> 7) * S_LEN + (size_t)(T2 & 127) * MROWS) * KC;
            int row = tid / 12, c = tid % 12;
            av = *(const uint4*)((const char*)Ag2 + (size_t)row * (KC * 2) + c * 16);
        }

        // --- readback + normalize + coalesced DRAM pass ---
        {
            const int row = tid >> 4;            // 0..15
            const int l16 = tid & 15;
            const float inv = rsum[row];
            const uint32_t srow = sSC + row * SROWB;
            float* orow = out + ((size_t)bh * S_LEN + (size_t)mt * MROWS + row) * S_LEN;
            #pragma unroll
            for (int i = 0; i < 16; i++) {
                const int chunk = l16 + i * 16;           // 16B = 8 halves
                uint32_t h[4];
                asm volatile("ld.shared.v4.b32 {%0,%1,%2,%3}, [%4];"
                             : "=r"(h[0]), "=r"(h[1]), "=r"(h[2]), "=r"(h[3])
                             : "r"(srow + chunk * 16));
                float2 f0 = __half22float2(*(__half2*)&h[0]);
                float2 f1 = __half22float2(*(__half2*)&h[1]);
                float2 f2 = __half22float2(*(__half2*)&h[2]);
                float2 f3 = __half22float2(*(__half2*)&h[3]);
                float4 o0 = make_float4(f0.x * inv, f0.y * inv, f1.x * inv, f1.y * inv);
                float4 o1 = make_float4(f2.x * inv, f2.y * inv, f3.x * inv, f3.y * inv);
                *(float4*)(orow + chunk * 8)     = o0;
                *(float4*)(orow + chunk * 8 + 4) = o1;
            }
        }
        __syncthreads();              // sc-smem + rsum reads complete

        if (hasNext && tid < 192) {
            int row = tid / 12, c = tid % 12;
            *(uint4*)(smraw + SM_A + row * SPADB + c * 16) = av;
        }
        __syncthreads();              // A(t+1) visible before next aF ldsm
    }
}

// ---------------------------------------------------------------------------
extern "C" void kernel_launch(void* const* d_in, const int* in_sizes, int n_in,
                              void* d_out, int out_size)
{
    const float* keys      = (const float*)d_in[0];
    const float* queries   = (const float*)d_in[1];
    const float* pos_key   = (const float*)d_in[2];
    const float* pos_query = (const float*)d_in[3];
    float* out = (float*)d_out;

    const size_t prep_total4 = (size_t)BHN * S_LEN * (KC / 4);
    prep_fp16<<<(unsigned)((prep_total4 + 255) / 256), 256>>>(keys, queries, pos_key, pos_query);

    cudaFuncSetAttribute(fused_attn, cudaFuncAttributeMaxDynamicSharedMemorySize, SM_TOT);
    fused_attn<<<NCTA, THREADS, SM_TOT>>>(out);
}